// round 3
// baseline (speedup 1.0000x reference)
#include <cuda_runtime.h>
#include <cstdint>

typedef unsigned long long u64;

#define Bn 1024
#define Tn 512
#define Ln 64
#define Nn 8
#define Hn 128
#define DIn 32
#define DOn 16
#define RROWS 8
#define PAIRS 4
#define NCTA (Bn / RROWS)   /* 128 */
#define NTHR 256
#define XFULL ((size_t)Bn * Tn * DOn)

// ---------------- shared memory layout (231,680 B < 232,448 B cap) ----------
struct __align__(16) Smem {
    float fW1t[Hn][68];    // f_W1 z-part transposed [j][k]; 68 == 4 (mod 32): conflict-free LDS.128
    float fW2t[Hn][132];   // f_W2 transposed; 132 == 4 (mod 32)
    float gW1t[Hn][68];
    float gW2t[Hn][132];
    float2 z2[PAIRS][Ln];  // state, row-pairs packed: .x = row 2p, .y = row 2p+1
    float2 h1f[PAIRS][Hn]; // f-path hidden 1 (aliased: geo in phase 3+, rh in readout)
    float2 h2f[PAIRS][Hn];
    float2 h1g[PAIRS][Hn]; // g-path hidden 1 (aliased: fo in phase 3+)
    float2 h2g[PAIRS][Hn];
    float rW2s[Hn * DOn];
    float2 dws[PAIRS][Nn];
};

// ---------------- f32x2 packed helpers ---------------------------------------
__device__ __forceinline__ u64 dup2f(float v) {
    u64 r; asm("mov.b64 %0,{%1,%1};" : "=l"(r) : "f"(v)); return r;
}
__device__ __forceinline__ u64 pk2(float lo, float hi) {
    u64 r; asm("mov.b64 %0,{%1,%2};" : "=l"(r) : "f"(lo), "f"(hi)); return r;
}
__device__ __forceinline__ void unpk2(u64 v, float& lo, float& hi) {
    asm("mov.b64 {%0,%1},%2;" : "=f"(lo), "=f"(hi) : "l"(v));
}
__device__ __forceinline__ u64 f2fma(u64 a, u64 b, u64 c) {
    u64 d; asm("fma.rn.f32x2 %0,%1,%2,%3;" : "=l"(d) : "l"(a), "l"(b), "l"(c)); return d;
}

// softplus(x) = max(x,0) + log1p(exp(-|x|))
__device__ __forceinline__ float softplus1(float x) {
    float e = __expf(-fabsf(x));
    return fmaxf(x, 0.f) + 0.69314718055994531f * __log2f(1.f + e);
}
// tanh(x) = 1 - 2/(exp(2x)+1)
__device__ __forceinline__ float tanh1(float x) {
    float e = __expf(2.f * x);
    return 1.f - __fdividef(2.f, e + 1.f);
}

// ---------------- layer kernels ----------------------------------------------
// Input layer with [t, z] input (K = 1 + 64). Thread j owns hidden neuron j, 4 pairs.
__device__ __forceinline__ void layer_tz(const float (&Wt)[Hn][68], float w0row,
                                         float bias, float tcur,
                                         const float2 (&acts)[PAIRS][Ln],
                                         float2 (&outp)[PAIRS][Hn], int j)
{
    u64 acc[PAIRS];
    u64 d0 = dup2f(fmaf(w0row, tcur, bias));
#pragma unroll
    for (int p = 0; p < PAIRS; p++) acc[p] = d0;
#pragma unroll 4
    for (int c = 0; c < Ln / 4; c++) {
        float4 w = *(const float4*)&Wt[j][4 * c];
        u64 w0 = dup2f(w.x), w1 = dup2f(w.y), w2 = dup2f(w.z), w3 = dup2f(w.w);
#pragma unroll
        for (int p = 0; p < PAIRS; p++) {
            ulonglong2 a0 = *(const ulonglong2*)&acts[p][4 * c];
            ulonglong2 a1 = *(const ulonglong2*)&acts[p][4 * c + 2];
            acc[p] = f2fma(w0, a0.x, acc[p]);
            acc[p] = f2fma(w1, a0.y, acc[p]);
            acc[p] = f2fma(w2, a1.x, acc[p]);
            acc[p] = f2fma(w3, a1.y, acc[p]);
        }
    }
#pragma unroll
    for (int p = 0; p < PAIRS; p++) {
        float lo, hi; unpk2(acc[p], lo, hi);
        outp[p][j] = make_float2(softplus1(lo), softplus1(hi));
    }
}

// Hidden->hidden layer, K = 128.
__device__ __forceinline__ void layer_h(const float (&Wt)[Hn][132], float bias,
                                        const float2 (&acts)[PAIRS][Hn],
                                        float2 (&outp)[PAIRS][Hn], int j)
{
    u64 acc[PAIRS];
    u64 d0 = dup2f(bias);
#pragma unroll
    for (int p = 0; p < PAIRS; p++) acc[p] = d0;
#pragma unroll 4
    for (int c = 0; c < Hn / 4; c++) {
        float4 w = *(const float4*)&Wt[j][4 * c];
        u64 w0 = dup2f(w.x), w1 = dup2f(w.y), w2 = dup2f(w.z), w3 = dup2f(w.w);
#pragma unroll
        for (int p = 0; p < PAIRS; p++) {
            ulonglong2 a0 = *(const ulonglong2*)&acts[p][4 * c];
            ulonglong2 a1 = *(const ulonglong2*)&acts[p][4 * c + 2];
            acc[p] = f2fma(w0, a0.x, acc[p]);
            acc[p] = f2fma(w1, a0.y, acc[p]);
            acc[p] = f2fma(w2, a1.x, acc[p]);
            acc[p] = f2fma(w3, a1.y, acc[p]);
        }
    }
#pragma unroll
    for (int p = 0; p < PAIRS; p++) {
        float lo, hi; unpk2(acc[p], lo, hi);
        outp[p][j] = make_float2(softplus1(lo), softplus1(hi));
    }
}

// Fused readout at time index tidx: x = relu(z @ rW1 + rb1) @ rW2 + rb2.
// Stage 1: 256 threads (neuron = tid&127, 2 pairs by team). Stage 2: (r,d,khalf)
// split with shfl_xor(16) k-reduction.
__device__ __forceinline__ void readout(int tidx, const float* __restrict__ rW1,
                                        float rb1v, float rb2v, Smem& sm, int tid,
                                        int rowbase, float* __restrict__ out)
{
    const int wg = tid & 127;
    const int p0 = (tid >> 7) * 2;
    u64 acc0 = dup2f(rb1v), acc1 = acc0;
#pragma unroll 8
    for (int c = 0; c < Ln / 2; c++) {
        float wl0 = __ldg(rW1 + (2 * c) * Hn + wg);
        float wl1 = __ldg(rW1 + (2 * c + 1) * Hn + wg);
        ulonglong2 a0 = *(const ulonglong2*)&sm.z2[p0][2 * c];
        ulonglong2 a1 = *(const ulonglong2*)&sm.z2[p0 + 1][2 * c];
        u64 w0 = dup2f(wl0), w1 = dup2f(wl1);
        acc0 = f2fma(w0, a0.x, acc0); acc0 = f2fma(w1, a0.y, acc0);
        acc1 = f2fma(w0, a1.x, acc1); acc1 = f2fma(w1, a1.y, acc1);
    }
    float lo, hi;
    unpk2(acc0, lo, hi); sm.h1f[p0][wg]     = make_float2(fmaxf(lo, 0.f), fmaxf(hi, 0.f));
    unpk2(acc1, lo, hi); sm.h1f[p0 + 1][wg] = make_float2(fmaxf(lo, 0.f), fmaxf(hi, 0.f));
    __syncthreads();
    // stage 2
    const int r = tid >> 5, rem = tid & 31, d = rem & 15, kh = rem >> 4;
    const int p = r >> 1, lane = r & 1;
    const float* hp = ((const float*)&sm.h1f[p][kh * 64]) + lane;
    const float* wp = &sm.rW2s[kh * 64 * DOn + d];
    float a = kh ? 0.f : rb2v;
#pragma unroll 8
    for (int k = 0; k < 64; k++)
        a = fmaf(hp[2 * k], wp[k * DOn], a);
    a += __shfl_xor_sync(0xffffffffu, a, 16);
    if (kh == 0) {
        size_t row = (size_t)rowbase + r;
        out[(row * Tn + tidx) * DOn + d] = a;
        if ((tidx & 7) == 0)
            out[XFULL + (row * (Tn / 8) + (tidx >> 3)) * DOn + d] = a;
    }
    __syncthreads();   // h1f reused next phase
}

// ---------------- main persistent kernel -------------------------------------
__global__ void __launch_bounds__(NTHR, 1)
sde_kernel(const float* __restrict__ init_noise, const float* __restrict__ dw_noise,
           const float* __restrict__ ts,   const float* __restrict__ embW,
           const float* __restrict__ embb, const float* __restrict__ fW1,
           const float* __restrict__ fb1,  const float* __restrict__ fW2,
           const float* __restrict__ fb2,  const float* __restrict__ fW3,
           const float* __restrict__ fb3,  const float* __restrict__ gW1,
           const float* __restrict__ gb1,  const float* __restrict__ gW2,
           const float* __restrict__ gb2,  const float* __restrict__ gW3,
           const float* __restrict__ gb3,  const float* __restrict__ rW1,
           const float* __restrict__ rb1,  const float* __restrict__ rW2,
           const float* __restrict__ rb2,  float* __restrict__ out)
{
    extern __shared__ __align__(16) char smraw[];
    Smem& sm = *reinterpret_cast<Smem*>(smraw);
    const int tid = threadIdx.x;
    const int wg = tid & 127;
    const int team = tid >> 7;
    const int rowbase = blockIdx.x * RROWS;

    // aliases over dead buffers (valid in phase 3/4 only)
    float2 (*fo)[Ln]  = reinterpret_cast<float2(*)[Ln]>(&sm.h1g[0][0]);
    float2 (*geo)[Ln] = reinterpret_cast<float2(*)[Ln]>(&sm.h1f[0][0]);

    // ---- stage SMEM-resident weights (team-split) ----
    if (team == 0) {
#pragma unroll 4
        for (int k = 0; k < Ln; k++) sm.fW1t[wg][k] = fW1[(k + 1) * Hn + wg];
#pragma unroll 4
        for (int k = 0; k < Hn; k++) sm.fW2t[wg][k] = fW2[k * Hn + wg];
    } else {
#pragma unroll 4
        for (int k = 0; k < Ln; k++) sm.gW1t[wg][k] = gW1[(k + 1) * Hn + wg];
#pragma unroll 4
        for (int k = 0; k < Hn; k++) sm.gW2t[wg][k] = gW2[k * Hn + wg];
    }
    for (int i = tid; i < Hn * DOn; i += NTHR) sm.rW2s[i] = rW2[i];

    // ---- per-thread register params (team-selected) ----
    const float w10 = team ? __ldg(gW1 + wg) : __ldg(fW1 + wg);
    const float b1  = team ? __ldg(gb1 + wg) : __ldg(fb1 + wg);
    const float b2  = team ? __ldg(gb2 + wg) : __ldg(fb2 + wg);
    const float bf3v = __ldg(fb3 + (wg & (Ln - 1)));      // team0 only
    const float2 bg3 = *(const float2*)(gb3 + 2 * tid);   // outputs 2*tid, 2*tid+1
    const float rb1v = __ldg(rb1 + wg);
    const float rb2v = __ldg(rb2 + (tid & 15));

    // ---- z0 = init_noise @ emb_W + emb_b (one (pair,l) per thread) ----
    {
        int l = tid & (Ln - 1), p = tid >> 6;
        float ax = __ldg(embb + l), ay = ax;
#pragma unroll 4
        for (int i = 0; i < DIn; i++) {
            float w = embW[i * Ln + l];
            ax = fmaf(init_noise[(rowbase + 2 * p) * DIn + i], w, ax);
            ay = fmaf(init_noise[(rowbase + 2 * p + 1) * DIn + i], w, ay);
        }
        sm.z2[p][l] = make_float2(ax, ay);
    }
    __syncthreads();
    readout(0, rW1, rb1v, rb2v, sm, tid, rowbase, out);

    // ---- 511 sequential Euler-Maruyama steps -------------------------------
    for (int s = 0; s < Tn - 1; s++) {
        const float tcur = __ldg(ts + s);
        const float dt = __ldg(ts + s + 1) - tcur;
        const float sq = sqrtf(dt);
        if (tid < 32) {   // Brownian increments, pair-packed (safe: 2 syncs before use)
            int p = tid >> 3, n = tid & 7;
            const float* dwp = dw_noise + ((size_t)s * Bn + rowbase + 2 * p) * Nn + n;
            sm.dws[p][n] = make_float2(dwp[0] * sq, dwp[Nn] * sq);
        }

        // phase 1: f and g first layers in parallel (team-split)
        if (team == 0) layer_tz(sm.fW1t, w10, b1, tcur, sm.z2, sm.h1f, wg);
        else           layer_tz(sm.gW1t, w10, b1, tcur, sm.z2, sm.h1g, wg);
        __syncthreads();
        // phase 2: second layers
        if (team == 0) layer_h(sm.fW2t, b2, sm.h1f, sm.h2f, wg);
        else           layer_h(sm.gW2t, b2, sm.h1g, sm.h2g, wg);
        __syncthreads();

        // phase 3: team0 does f3 first, then everyone does the g3 split
        if (team == 0) {
            int l = wg & (Ln - 1), q0 = (wg >> 6) * 2;
            u64 a0 = dup2f(bf3v), a1 = a0;
#pragma unroll 8
            for (int k = 0; k < Hn; k++) {
                u64 wd = dup2f(__ldg(fW3 + k * Ln + l));
                a0 = f2fma(wd, *(const u64*)&sm.h2f[q0][k], a0);
                a1 = f2fma(wd, *(const u64*)&sm.h2f[q0 + 1][k], a1);
            }
            float lo, hi;
            unpk2(a0, lo, hi); fo[q0][l]     = make_float2(tanh1(lo), tanh1(hi));
            unpk2(a1, lo, hi); fo[q0 + 1][l] = make_float2(tanh1(lo), tanh1(hi));
        }
        {
            // g3: thread owns outputs {2*tid, 2*tid+1}, all 4 pairs, full K.
            u64 acc[PAIRS][2];
            u64 ba = dup2f(bg3.x), bb = dup2f(bg3.y);
#pragma unroll
            for (int p = 0; p < PAIRS; p++) { acc[p][0] = ba; acc[p][1] = bb; }
            const float* gp = gW3 + 2 * tid;
#pragma unroll 4
            for (int c = 0; c < Hn / 2; c++) {
                float2 wa = *(const float2*)(gp + (size_t)(2 * c) * (Ln * Nn));
                float2 wb = *(const float2*)(gp + (size_t)(2 * c + 1) * (Ln * Nn));
                u64 wa0 = dup2f(wa.x), wa1 = dup2f(wa.y);
                u64 wb0 = dup2f(wb.x), wb1 = dup2f(wb.y);
#pragma unroll
                for (int p = 0; p < PAIRS; p++) {
                    ulonglong2 h = *(const ulonglong2*)&sm.h2g[p][2 * c];
                    acc[p][0] = f2fma(wa0, h.x, acc[p][0]);
                    acc[p][1] = f2fma(wa1, h.x, acc[p][1]);
                    acc[p][0] = f2fma(wb0, h.y, acc[p][0]);
                    acc[p][1] = f2fma(wb1, h.y, acc[p][1]);
                }
            }
            // tanh -> * dW -> reduce over this thread's 2 n's, then 4-thread shfl tree
            const int l = tid >> 2, ns = (tid & 3) * 2;
            const u64 one2 = dup2f(1.f);
            const u64 zero2 = dup2f(0.f);
#pragma unroll
            for (int p = 0; p < PAIRS; p++) {
                float x0, x1, y0, y1;
                unpk2(acc[p][0], x0, x1);
                unpk2(acc[p][1], y0, y1);
                u64 t0 = pk2(tanh1(x0), tanh1(x1));
                u64 t1 = pk2(tanh1(y0), tanh1(y1));
                u64 pa = f2fma(t0, *(const u64*)&sm.dws[p][ns], zero2);
                pa = f2fma(t1, *(const u64*)&sm.dws[p][ns + 1], pa);
                u64 o1 = __shfl_xor_sync(0xffffffffu, pa, 1);
                pa = f2fma(one2, o1, pa);
                u64 o2 = __shfl_xor_sync(0xffffffffu, pa, 2);
                pa = f2fma(one2, o2, pa);
                if ((tid & 3) == 0) *(u64*)&geo[p][l] = pa;
            }
        }
        __syncthreads();

        // phase 4: z update
        if (tid < Ln) {
            u64 dt2 = dup2f(dt);
            const u64 one2 = dup2f(1.f);
#pragma unroll
            for (int p = 0; p < PAIRS; p++) {
                u64 z = *(const u64*)&sm.z2[p][tid];
                z = f2fma(*(const u64*)&fo[p][tid], dt2, z);
                z = f2fma(one2, *(const u64*)&geo[p][tid], z);
                *(u64*)&sm.z2[p][tid] = z;
            }
        }
        __syncthreads();
        readout(s + 1, rW1, rb1v, rb2v, sm, tid, rowbase, out);
    }
}

extern "C" void kernel_launch(void* const* d_in, const int* in_sizes, int n_in,
                              void* d_out, int out_size) {
    (void)in_sizes; (void)n_in; (void)out_size;
    cudaFuncSetAttribute(sde_kernel, cudaFuncAttributeMaxDynamicSharedMemorySize,
                         (int)sizeof(Smem));
    sde_kernel<<<NCTA, NTHR, sizeof(Smem)>>>(
        (const float*)d_in[0],  (const float*)d_in[1],  (const float*)d_in[2],
        (const float*)d_in[3],  (const float*)d_in[4],  (const float*)d_in[5],
        (const float*)d_in[6],  (const float*)d_in[7],  (const float*)d_in[8],
        (const float*)d_in[9],  (const float*)d_in[10], (const float*)d_in[11],
        (const float*)d_in[12], (const float*)d_in[13], (const float*)d_in[14],
        (const float*)d_in[15], (const float*)d_in[16], (const float*)d_in[17],
        (const float*)d_in[18], (const float*)d_in[19], (const float*)d_in[20],
        (float*)d_out);
}

// round 4
// speedup vs baseline: 1.4383x; 1.4383x over previous
#include <cuda_runtime.h>
#include <cstdint>

typedef unsigned long long u64;

#define Bn 1024
#define Tn 512
#define Ln 64
#define Nn 8
#define Hn 128
#define DIn 32
#define DOn 16
#define RROWS 8
#define PAIRS 4
#define NCTA (Bn / RROWS)   /* 128 */
#define NTHR 256
#define XFULL ((size_t)Bn * Tn * DOn)

// ---------------- shared memory layout (231,680 B < 232,448 B cap) ----------
struct __align__(16) Smem {
    float fW1t[Hn][68];    // f_W1 z-part transposed [j][k]; 68 == 4 (mod 32): conflict-free LDS.128
    float fW2t[Hn][132];   // f_W2 transposed; 132 == 4 (mod 32)
    float gW1t[Hn][68];
    float gW2t[Hn][132];
    float2 z2[PAIRS][Ln];  // state, row-pairs packed: .x = row 2p, .y = row 2p+1
    float2 h1f[PAIRS][Hn]; // f hidden-1 (alias: fo in phase>=3; readout scratch)
    float2 h2f[PAIRS][Hn]; // f hidden-2 (alias: geo in phase>=5)
    float2 h1g[PAIRS][Hn];
    float2 h2g[PAIRS][Hn];
    float rW2s[Hn * DOn];
    float2 dws[PAIRS][Nn];
};

// ---------------- f32x2 packed helpers ---------------------------------------
__device__ __forceinline__ u64 dup2f(float v) {
    u64 r; asm("mov.b64 %0,{%1,%1};" : "=l"(r) : "f"(v)); return r;
}
__device__ __forceinline__ u64 pk2(float lo, float hi) {
    u64 r; asm("mov.b64 %0,{%1,%2};" : "=l"(r) : "f"(lo), "f"(hi)); return r;
}
__device__ __forceinline__ void unpk2(u64 v, float& lo, float& hi) {
    asm("mov.b64 {%0,%1},%2;" : "=f"(lo), "=f"(hi) : "l"(v));
}
__device__ __forceinline__ u64 f2fma(u64 a, u64 b, u64 c) {
    u64 d; asm("fma.rn.f32x2 %0,%1,%2,%3;" : "=l"(d) : "l"(a), "l"(b), "l"(c)); return d;
}

// softplus(x) = max(x,0) + log1p(exp(-|x|))
__device__ __forceinline__ float softplus1(float x) {
    float e = __expf(-fabsf(x));
    return fmaxf(x, 0.f) + 0.69314718055994531f * __log2f(1.f + e);
}
// tanh(x) = 1 - 2/(exp(2x)+1)
__device__ __forceinline__ float tanh1(float x) {
    float e = __expf(2.f * x);
    return 1.f - __fdividef(2.f, e + 1.f);
}

// ---------------- layer kernels (pair-split: thread does 2 pairs) ------------
// Input layer with [t, z] input (K = 1 + 64). Thread j owns hidden neuron j.
__device__ __forceinline__ void layer_tz(const float (&Wt)[Hn][68], float w0row,
                                         float bias, float tcur,
                                         const float2 (&acts)[PAIRS][Ln],
                                         float2 (&outp)[PAIRS][Hn], int j, int p0)
{
    const u64 one2 = dup2f(1.f);
    u64 d0 = dup2f(fmaf(w0row, tcur, bias));
    u64 z0 = dup2f(0.f);
    u64 aA[2] = { d0, d0 }, aB[2] = { z0, z0 };   // split chains per pair
#pragma unroll 4
    for (int c = 0; c < Ln / 4; c++) {
        float4 w = *(const float4*)&Wt[j][4 * c];
        u64 w0 = dup2f(w.x), w1 = dup2f(w.y), w2 = dup2f(w.z), w3 = dup2f(w.w);
#pragma unroll
        for (int e = 0; e < 2; e++) {
            ulonglong2 x0 = *(const ulonglong2*)&acts[p0 + e][4 * c];
            ulonglong2 x1 = *(const ulonglong2*)&acts[p0 + e][4 * c + 2];
            aA[e] = f2fma(w0, x0.x, aA[e]);
            aB[e] = f2fma(w1, x0.y, aB[e]);
            aA[e] = f2fma(w2, x1.x, aA[e]);
            aB[e] = f2fma(w3, x1.y, aB[e]);
        }
    }
#pragma unroll
    for (int e = 0; e < 2; e++) {
        u64 t = f2fma(one2, aB[e], aA[e]);
        float lo, hi; unpk2(t, lo, hi);
        outp[p0 + e][j] = make_float2(softplus1(lo), softplus1(hi));
    }
}

// Hidden->hidden layer, K = 128.
__device__ __forceinline__ void layer_h(const float (&Wt)[Hn][132], float bias,
                                        const float2 (&acts)[PAIRS][Hn],
                                        float2 (&outp)[PAIRS][Hn], int j, int p0)
{
    const u64 one2 = dup2f(1.f);
    u64 d0 = dup2f(bias), z0 = dup2f(0.f);
    u64 aA[2] = { d0, d0 }, aB[2] = { z0, z0 };
#pragma unroll 4
    for (int c = 0; c < Hn / 4; c++) {
        float4 w = *(const float4*)&Wt[j][4 * c];
        u64 w0 = dup2f(w.x), w1 = dup2f(w.y), w2 = dup2f(w.z), w3 = dup2f(w.w);
#pragma unroll
        for (int e = 0; e < 2; e++) {
            ulonglong2 x0 = *(const ulonglong2*)&acts[p0 + e][4 * c];
            ulonglong2 x1 = *(const ulonglong2*)&acts[p0 + e][4 * c + 2];
            aA[e] = f2fma(w0, x0.x, aA[e]);
            aB[e] = f2fma(w1, x0.y, aB[e]);
            aA[e] = f2fma(w2, x1.x, aA[e]);
            aB[e] = f2fma(w3, x1.y, aB[e]);
        }
    }
#pragma unroll
    for (int e = 0; e < 2; e++) {
        u64 t = f2fma(one2, aB[e], aA[e]);
        float lo, hi; unpk2(t, lo, hi);
        outp[p0 + e][j] = make_float2(softplus1(lo), softplus1(hi));
    }
}

// Fused readout at time index tidx: x = relu(z @ rW1 + rb1) @ rW2 + rb2.
__device__ __forceinline__ void readout(int tidx, const float* __restrict__ rW1,
                                        float rb1v, float rb2v, Smem& sm, int tid,
                                        int rowbase, float* __restrict__ out)
{
    const u64 one2 = dup2f(1.f);
    const int wg = tid & 127;
    const int p0 = (tid >> 7) * 2;
    const float* rp = rW1 + wg;
    u64 bi = dup2f(rb1v), z0 = dup2f(0.f);
    u64 aA[2] = { bi, bi }, aB[2] = { z0, z0 };
#pragma unroll 4
    for (int c = 0; c < Ln / 2; c++) {
        u64 w0 = dup2f(__ldg(rp + (2 * c) * Hn));
        u64 w1 = dup2f(__ldg(rp + (2 * c + 1) * Hn));
#pragma unroll
        for (int e = 0; e < 2; e++) {
            ulonglong2 a = *(const ulonglong2*)&sm.z2[p0 + e][2 * c];
            aA[e] = f2fma(w0, a.x, aA[e]);
            aB[e] = f2fma(w1, a.y, aB[e]);
        }
    }
#pragma unroll
    for (int e = 0; e < 2; e++) {
        u64 t = f2fma(one2, aB[e], aA[e]);
        float lo, hi; unpk2(t, lo, hi);
        sm.h1f[p0 + e][wg] = make_float2(fmaxf(lo, 0.f), fmaxf(hi, 0.f));
    }
    __syncthreads();
    // stage 2: r = row (0..7), d = output dim, kh = k-half; shfl_xor(16) reduce
    const int r = tid >> 5, rem = tid & 31, d = rem & 15, kh = rem >> 4;
    const int p = r >> 1, lane = r & 1;
    const float* hp = ((const float*)&sm.h1f[p][kh * 64]) + lane;
    const float* wp = &sm.rW2s[kh * 64 * DOn + d];
    float a = kh ? 0.f : rb2v;
#pragma unroll 8
    for (int k = 0; k < 64; k++)
        a = fmaf(hp[2 * k], wp[k * DOn], a);
    a += __shfl_xor_sync(0xffffffffu, a, 16);
    if (kh == 0) {
        size_t row = (size_t)rowbase + r;
        out[(row * Tn + tidx) * DOn + d] = a;
        if ((tidx & 7) == 0)
            out[XFULL + (row * (Tn / 8) + (tidx >> 3)) * DOn + d] = a;
    }
    __syncthreads();   // h1f reused next phase
}

// ---------------- main persistent kernel -------------------------------------
__global__ void __launch_bounds__(NTHR, 1)
sde_kernel(const float* __restrict__ init_noise, const float* __restrict__ dw_noise,
           const float* __restrict__ ts,   const float* __restrict__ embW,
           const float* __restrict__ embb, const float* __restrict__ fW1,
           const float* __restrict__ fb1,  const float* __restrict__ fW2,
           const float* __restrict__ fb2,  const float* __restrict__ fW3,
           const float* __restrict__ fb3,  const float* __restrict__ gW1,
           const float* __restrict__ gb1,  const float* __restrict__ gW2,
           const float* __restrict__ gb2,  const float* __restrict__ gW3,
           const float* __restrict__ gb3,  const float* __restrict__ rW1,
           const float* __restrict__ rb1,  const float* __restrict__ rW2,
           const float* __restrict__ rb2,  float* __restrict__ out)
{
    extern __shared__ __align__(16) char smraw[];
    Smem& sm = *reinterpret_cast<Smem*>(smraw);
    const int tid = threadIdx.x;
    const int wg = tid & 127;
    const int team = tid >> 7;
    const int p0 = team * 2;
    const int rowbase = blockIdx.x * RROWS;

    // aliases over dead buffers
    float2 (*fo)[Ln]  = reinterpret_cast<float2(*)[Ln]>(&sm.h1f[0][0]); // live ph3..zupd
    float2 (*geo)[Ln] = reinterpret_cast<float2(*)[Ln]>(&sm.h2f[0][0]); // live ph5..zupd

    // ---- stage SMEM-resident weights (team-split) ----
    if (team == 0) {
#pragma unroll 4
        for (int k = 0; k < Ln; k++) sm.fW1t[wg][k] = fW1[(k + 1) * Hn + wg];
#pragma unroll 4
        for (int k = 0; k < Hn; k++) sm.fW2t[wg][k] = fW2[k * Hn + wg];
    } else {
#pragma unroll 4
        for (int k = 0; k < Ln; k++) sm.gW1t[wg][k] = gW1[(k + 1) * Hn + wg];
#pragma unroll 4
        for (int k = 0; k < Hn; k++) sm.gW2t[wg][k] = gW2[k * Hn + wg];
    }
    for (int i = tid; i < Hn * DOn; i += NTHR) sm.rW2s[i] = rW2[i];

    // ---- per-thread register params (all threads run both f and g paths) ----
    const float w10f = __ldg(fW1 + wg), w10g = __ldg(gW1 + wg);
    const float bf1 = __ldg(fb1 + wg), bf2 = __ldg(fb2 + wg);
    const float bg1 = __ldg(gb1 + wg), bg2 = __ldg(gb2 + wg);
    const float bf3v = __ldg(fb3 + (tid & (Ln - 1)));
    float bg3a[4];
#pragma unroll
    for (int i = 0; i < 4; i++) bg3a[i] = __ldg(gb3 + 4 * wg + i);
    const float rb1v = __ldg(rb1 + wg), rb2v = __ldg(rb2 + (tid & 15));

    // ---- z0 = init_noise @ emb_W + emb_b: thread = (pair, l) ----
    {
        int l = tid & (Ln - 1), p = tid >> 6;
        float ax = __ldg(embb + l), ay = ax;
#pragma unroll 4
        for (int i = 0; i < DIn; i++) {
            float w = embW[i * Ln + l];
            ax = fmaf(init_noise[(rowbase + 2 * p) * DIn + i], w, ax);
            ay = fmaf(init_noise[(rowbase + 2 * p + 1) * DIn + i], w, ay);
        }
        sm.z2[p][l] = make_float2(ax, ay);
    }
    __syncthreads();
    readout(0, rW1, rb1v, rb2v, sm, tid, rowbase, out);

    // ---- 511 sequential Euler-Maruyama steps -------------------------------
    for (int s = 0; s < Tn - 1; s++) {
        const float tcur = __ldg(ts + s);
        const float dt = __ldg(ts + s + 1) - tcur;
        const float sq = sqrtf(dt);
        if (tid < 32) {   // Brownian increments, pair-packed (consumed after >=2 syncs)
            int p = tid >> 3, n = tid & 7;
            const float* dwp = dw_noise + ((size_t)s * Bn + rowbase + 2 * p) * Nn + n;
            sm.dws[p][n] = make_float2(dwp[0] * sq, dwp[Nn] * sq);
        }

        // phase 1: f layer 1 (all threads, own 2 pairs)
        layer_tz(sm.fW1t, w10f, bf1, tcur, sm.z2, sm.h1f, wg, p0);
        __syncthreads();
        // phase 2: f layer 2
        layer_h(sm.fW2t, bf2, sm.h1f, sm.h2f, wg, p0);
        __syncthreads();
        // phase 3: f layer 3 (thread = (l, q), 1 output) + g layer 1
        {
            const u64 one2 = dup2f(1.f);
            int l = tid & (Ln - 1), q = tid >> 6;
            const float* fp = fW3 + l;
            u64 a0 = dup2f(bf3v), a1 = dup2f(0.f);
#pragma unroll 8
            for (int k = 0; k < Hn; k += 2) {
                u64 w0 = dup2f(__ldg(fp + k * Ln));
                u64 w1 = dup2f(__ldg(fp + (k + 1) * Ln));
                a0 = f2fma(w0, *(const u64*)&sm.h2f[q][k], a0);
                a1 = f2fma(w1, *(const u64*)&sm.h2f[q][k + 1], a1);
            }
            a0 = f2fma(one2, a1, a0);
            float lo, hi; unpk2(a0, lo, hi);
            fo[q][l] = make_float2(tanh1(lo), tanh1(hi));
        }
        layer_tz(sm.gW1t, w10g, bg1, tcur, sm.z2, sm.h1g, wg, p0);
        __syncthreads();
        // phase 4: g layer 2
        layer_h(sm.gW2t, bg2, sm.h1g, sm.h2g, wg, p0);
        __syncthreads();

        // phase 5: g layer 3 + einsum partials. Thread owns outputs 4*wg..4*wg+3
        // for its 2 pairs. gW3 float4 loads, pointer-increment addressing.
        {
            const u64 one2 = dup2f(1.f);
            u64 acc[2][4];
#pragma unroll
            for (int i = 0; i < 4; i++) {
                u64 b = dup2f(bg3a[i]);
                acc[0][i] = b; acc[1][i] = b;
            }
            const float4* g4 = reinterpret_cast<const float4*>(gW3) + wg;
#pragma unroll 4
            for (int c = 0; c < Hn / 2; c++) {
                float4 wa = __ldg(g4 + (2 * c) * (Ln * Nn / 4));
                float4 wb = __ldg(g4 + (2 * c + 1) * (Ln * Nn / 4));
                u64 wa0 = dup2f(wa.x), wa1 = dup2f(wa.y), wa2 = dup2f(wa.z), wa3 = dup2f(wa.w);
                u64 wb0 = dup2f(wb.x), wb1 = dup2f(wb.y), wb2 = dup2f(wb.z), wb3 = dup2f(wb.w);
#pragma unroll
                for (int e = 0; e < 2; e++) {
                    ulonglong2 h = *(const ulonglong2*)&sm.h2g[p0 + e][2 * c];
                    acc[e][0] = f2fma(wa0, h.x, acc[e][0]);
                    acc[e][1] = f2fma(wa1, h.x, acc[e][1]);
                    acc[e][2] = f2fma(wa2, h.x, acc[e][2]);
                    acc[e][3] = f2fma(wa3, h.x, acc[e][3]);
                    acc[e][0] = f2fma(wb0, h.y, acc[e][0]);
                    acc[e][1] = f2fma(wb1, h.y, acc[e][1]);
                    acc[e][2] = f2fma(wb2, h.y, acc[e][2]);
                    acc[e][3] = f2fma(wb3, h.y, acc[e][3]);
                }
            }
            // tanh -> * dW -> local reduce over 4 n's -> shfl_xor(1) -> geo
            const int l = wg >> 1, nbase = (wg & 1) * 4;
#pragma unroll
            for (int e = 0; e < 2; e++) {
                int p = p0 + e;
                u64 pa = dup2f(0.f);
#pragma unroll
                for (int i = 0; i < 4; i++) {
                    float lo, hi; unpk2(acc[e][i], lo, hi);
                    u64 tv = pk2(tanh1(lo), tanh1(hi));
                    pa = f2fma(tv, *(const u64*)&sm.dws[p][nbase + i], pa);
                }
                u64 o1 = __shfl_xor_sync(0xffffffffu, pa, 1);
                pa = f2fma(one2, o1, pa);
                if ((wg & 1) == 0) *(u64*)&geo[p][l] = pa;
            }
        }
        __syncthreads();

        // phase 6: z update — thread = (pair, l)
        {
            int l = tid & (Ln - 1), p = tid >> 6;
            const u64 one2 = dup2f(1.f);
            u64 dt2 = dup2f(dt);
            u64 z = *(const u64*)&sm.z2[p][l];
            z = f2fma(*(const u64*)&fo[p][l], dt2, z);
            z = f2fma(one2, *(const u64*)&geo[p][l], z);
            *(u64*)&sm.z2[p][l] = z;
        }
        __syncthreads();
        readout(s + 1, rW1, rb1v, rb2v, sm, tid, rowbase, out);
    }
}

extern "C" void kernel_launch(void* const* d_in, const int* in_sizes, int n_in,
                              void* d_out, int out_size) {
    (void)in_sizes; (void)n_in; (void)out_size;
    cudaFuncSetAttribute(sde_kernel, cudaFuncAttributeMaxDynamicSharedMemorySize,
                         (int)sizeof(Smem));
    sde_kernel<<<NCTA, NTHR, sizeof(Smem)>>>(
        (const float*)d_in[0],  (const float*)d_in[1],  (const float*)d_in[2],
        (const float*)d_in[3],  (const float*)d_in[4],  (const float*)d_in[5],
        (const float*)d_in[6],  (const float*)d_in[7],  (const float*)d_in[8],
        (const float*)d_in[9],  (const float*)d_in[10], (const float*)d_in[11],
        (const float*)d_in[12], (const float*)d_in[13], (const float*)d_in[14],
        (const float*)d_in[15], (const float*)d_in[16], (const float*)d_in[17],
        (const float*)d_in[18], (const float*)d_in[19], (const float*)d_in[20],
        (float*)d_out);
}